// round 4
// baseline (speedup 1.0000x reference)
#include <cuda_runtime.h>
#include <cuda_fp16.h>
#include <math.h>

#define VD 256
#define VH 240
#define VW 320
#define NPIX (VH * VW)
#define XB (VW / 32)   // 10 x-blocks

// Density volume, fp16, tiled layout: [y][x>>5][z][x&31]
// addr(y,x,z) = ((y*XB + (x>>5))*VD + z)*32 + (x&31)
__device__ __half g_E[(size_t)NPIX * VD];   // 39.3 MB

// ---------------------------------------------------------------------------
// Pass 1: per-pixel softmax denominator + scale, then write density volume
// (exp(f) * K) in fp16 tiled layout. Loop 2 re-reads fv — L2-resident after
// loop 1 (78 MB < 126 MB L2). Warp = 32 consecutive x → both the fv reads
// (128B) and the g_E writes (64B at fixed z) are fully coalesced.
// ---------------------------------------------------------------------------
__global__ void __launch_bounds__(256) pass1_kernel(const float* __restrict__ fv,
                                                    const float* __restrict__ lmv) {
    int pix = blockIdx.x * blockDim.x + threadIdx.x;
    if (pix >= NPIX) return;
    const float* p = fv + pix;

    float s0 = 0.f, s1 = 0.f, s2 = 0.f, s3 = 0.f;
#pragma unroll 8
    for (int z = 0; z < VD; z += 4) {
        s0 += __expf(p[(z + 0) * NPIX]);
        s1 += __expf(p[(z + 1) * NPIX]);
        s2 += __expf(p[(z + 2) * NPIX]);
        s3 += __expf(p[(z + 3) * NPIX]);
    }
    float s = (s0 + s1) + (s2 + s3);
    float mv = lmv[pix];
    float K = ((mv > 0.f ? mv : 0.f) + 0.01f) / s;

    int y = pix / VW;
    int x = pix - y * VW;
    __half* e = g_E + ((size_t)(y * XB + (x >> 5)) * VD) * 32 + (x & 31);

#pragma unroll 8
    for (int z = 0; z < VD; z++) {
        e[z * 32] = __float2half_rn(__expf(p[z * NPIX]) * K);
    }
}

// ---------------------------------------------------------------------------
// Pass 2: project point, trilinear-gather density from the fp16 tiled volume.
// Each (y,z) corner group is an x-adjacent half pair -> 1 L1 sector.
// ---------------------------------------------------------------------------
__device__ __forceinline__ size_t eaddr(int y, int x, int z) {
    return ((size_t)(y * XB + (x >> 5)) * VD + z) * 32 + (x & 31);
}

__global__ void __launch_bounds__(256) pass2_kernel(const float* __restrict__ pts,
                                                    const float* __restrict__ intr,
                                                    const int* __restrict__ Hp,
                                                    const int* __restrict__ Wp,
                                                    const int* __restrict__ dminp,
                                                    const int* __restrict__ dmaxp,
                                                    float* __restrict__ out,
                                                    int n) {
    int i = blockIdx.x * blockDim.x + threadIdx.x;
    if (i >= n) return;

    float X = pts[3 * i + 0];
    float Y = pts[3 * i + 1];
    float Z = pts[3 * i + 2];

    float fx = intr[0], cx = intr[2];
    float fy = intr[4], cy = intr[5];
    float Himg = (float)(*Hp);
    float Wimg = (float)(*Wp);
    float dmin = (float)(*dminp);
    float dmax = (float)(*dmaxp);

    // projection: p2d = [fx*X + cx*Z, fy*Y + cy*Z, Z]
    float px = fx * X + cx * Z;
    float py = fy * Y + cy * Z;
    float pz = Z;
    float inv_e = 1.0f / (pz + 1e-10f);
    float inv = 1.0f / pz;

    float gx = (px * inv_e / Wimg - 0.5f) * 2.0f;
    float gy = (py * inv_e / Himg - 0.5f) * 2.0f;
    float gz = ((inv - dmin) / (dmax - dmin) - 0.5f) * 2.0f;

    // grid_sample: align_corners=True, padding=border
    float fxc = fminf(fmaxf((gx + 1.0f) * 0.5f * (float)(VW - 1), 0.0f), (float)(VW - 1));
    float fyc = fminf(fmaxf((gy + 1.0f) * 0.5f * (float)(VH - 1), 0.0f), (float)(VH - 1));
    float fzc = fminf(fmaxf((gz + 1.0f) * 0.5f * (float)(VD - 1), 0.0f), (float)(VD - 1));

    int x0 = (int)floorf(fxc); int x1 = min(x0 + 1, VW - 1);
    int y0 = (int)floorf(fyc); int y1 = min(y0 + 1, VH - 1);
    int z0 = (int)floorf(fzc); int z1 = min(z0 + 1, VD - 1);
    float wx = fxc - (float)x0;
    float wy = fyc - (float)y0;
    float wz = fzc - (float)z0;

    // 8 corner density loads (fp16). Issue all loads before any use.
    float d000 = __half2float(g_E[eaddr(y0, x0, z0)]);
    float d001 = __half2float(g_E[eaddr(y0, x1, z0)]);
    float d010 = __half2float(g_E[eaddr(y1, x0, z0)]);
    float d011 = __half2float(g_E[eaddr(y1, x1, z0)]);
    float d100 = __half2float(g_E[eaddr(y0, x0, z1)]);
    float d101 = __half2float(g_E[eaddr(y0, x1, z1)]);
    float d110 = __half2float(g_E[eaddr(y1, x0, z1)]);
    float d111 = __half2float(g_E[eaddr(y1, x1, z1)]);

    float c00 = d000 + (d001 - d000) * wx;  // z0,y0
    float c01 = d010 + (d011 - d010) * wx;  // z0,y1
    float c10 = d100 + (d101 - d100) * wx;  // z1,y0
    float c11 = d110 + (d111 - d110) * wx;  // z1,y1
    float c0 = c00 + (c01 - c00) * wy;      // z0
    float c1 = c10 + (c11 - c10) * wy;      // z1
    out[i] = c0 + (c1 - c0) * wz;
}

extern "C" void kernel_launch(void* const* d_in, const int* in_sizes, int n_in,
                              void* d_out, int out_size) {
    const float* fv   = (const float*)d_in[0];  // feature_volume [1,1,256,240,320]
    const float* lmv  = (const float*)d_in[1];  // learnable_max_value [1,1,1,240,320]
    const float* intr = (const float*)d_in[2];  // [1,3,3]
    const float* pts  = (const float*)d_in[3];  // [1,8192,128,3]
    const int*   Hp   = (const int*)d_in[4];
    const int*   Wp   = (const int*)d_in[5];
    const int*   dmin = (const int*)d_in[6];
    const int*   dmax = (const int*)d_in[7];

    pass1_kernel<<<(NPIX + 255) / 256, 256>>>(fv, lmv);

    int n = out_size;  // 1*8192*128 points
    pass2_kernel<<<(n + 255) / 256, 256>>>(pts, intr, Hp, Wp, dmin, dmax,
                                           (float*)d_out, n);
}

// round 5
// speedup vs baseline: 1.6021x; 1.6021x over previous
#include <cuda_runtime.h>
#include <cuda_fp16.h>
#include <math.h>

#define VD 256
#define VH 240
#define VW 320
#define NPIX (VH * VW)
#define XB (VW / 32)      // 10 x-blocks
#define ZB2 (VD / 2)      // 128 z-pairs

// Density volume, fp16, z-paired tiled layout.
// half2 element index for (y, x, zb=z>>1):
//   (( (y*XB + (x>>5)) * 128 + zb ) * 32 + (x&31))
// -> the two z values (2*zb, 2*zb+1) sit in one 4B half2;
//    x-neighbors are 4B apart. A (2x)x(2z) corner group = 8B when z0 even.
__device__ __half2 g_E2[(size_t)NPIX * ZB2];   // 39.3 MB

// ---------------------------------------------------------------------------
// Pass 1 (single sweep): block = one (y, x-block) column group, 256 threads.
// lane = x within the 32-block, warp w owns z in [32w, 32w+32).
// Each thread keeps its 32 exp values in registers, smem-reduce the softmax
// denominator across warps, then write fp16 density as coalesced half2.
// ---------------------------------------------------------------------------
__global__ void __launch_bounds__(256) pass1_kernel(const float* __restrict__ fv,
                                                    const float* __restrict__ lmv) {
    int blk  = blockIdx.x;            // y*XB + xb, 2400 blocks
    int y    = blk / XB;
    int xb   = blk - y * XB;
    int lane = threadIdx.x & 31;
    int wid  = threadIdx.x >> 5;
    int x    = (xb << 5) + lane;

    const float* p = fv + (size_t)y * VW + x;   // + z*NPIX per slice

    float e[32];
    float s = 0.f;
#pragma unroll
    for (int i = 0; i < 32; i++) {
        int z = (wid << 5) + i;
        e[i] = __expf(p[(size_t)z * NPIX]);
        s += e[i];
    }

    __shared__ float part[8][32];
    part[wid][lane] = s;
    __syncthreads();

    float tot = 0.f;
#pragma unroll
    for (int w = 0; w < 8; w++) tot += part[w][lane];

    float mv = lmv[y * VW + x];
    float K  = (fmaxf(mv, 0.f) + 0.01f) / tot;

    // write 16 half2 (z-pairs), each a 128B coalesced warp store
    __half2* dst = g_E2 + ((size_t)blk * 128 + (wid << 4)) * 32 + lane;
#pragma unroll
    for (int i = 0; i < 16; i++) {
        dst[(size_t)i * 32] = __floats2half2_rn(e[2 * i] * K, e[2 * i + 1] * K);
    }
}

// ---------------------------------------------------------------------------
// Pass 2: project point, trilinear-gather from z-paired fp16 volume.
// 8 corners come from 8 half2 loads; when z0 is even the two zb's coincide
// and a whole (x,z) corner quad lives in one 8B span -> ~3 sectors/point.
// ---------------------------------------------------------------------------
__device__ __forceinline__ size_t e2idx(int y, int x, int zb) {
    return ((size_t)(y * XB + (x >> 5)) * 128 + zb) * 32 + (x & 31);
}

__global__ void __launch_bounds__(256) pass2_kernel(const float* __restrict__ pts,
                                                    const float* __restrict__ intr,
                                                    const int* __restrict__ Hp,
                                                    const int* __restrict__ Wp,
                                                    const int* __restrict__ dminp,
                                                    const int* __restrict__ dmaxp,
                                                    float* __restrict__ out,
                                                    int n) {
    int i = blockIdx.x * blockDim.x + threadIdx.x;
    if (i >= n) return;

    float X = pts[3 * i + 0];
    float Y = pts[3 * i + 1];
    float Z = pts[3 * i + 2];

    float fx = intr[0], cx = intr[2];
    float fy = intr[4], cy = intr[5];
    float Himg = (float)(*Hp);
    float Wimg = (float)(*Wp);
    float dmin = (float)(*dminp);
    float dmax = (float)(*dmaxp);

    float px = fx * X + cx * Z;
    float py = fy * Y + cy * Z;
    float pz = Z;
    float inv_e = 1.0f / (pz + 1e-10f);
    float inv = 1.0f / pz;

    float gx = (px * inv_e / Wimg - 0.5f) * 2.0f;
    float gy = (py * inv_e / Himg - 0.5f) * 2.0f;
    float gz = ((inv - dmin) / (dmax - dmin) - 0.5f) * 2.0f;

    float fxc = fminf(fmaxf((gx + 1.0f) * 0.5f * (float)(VW - 1), 0.0f), (float)(VW - 1));
    float fyc = fminf(fmaxf((gy + 1.0f) * 0.5f * (float)(VH - 1), 0.0f), (float)(VH - 1));
    float fzc = fminf(fmaxf((gz + 1.0f) * 0.5f * (float)(VD - 1), 0.0f), (float)(VD - 1));

    int x0 = (int)floorf(fxc); int x1 = min(x0 + 1, VW - 1);
    int y0 = (int)floorf(fyc); int y1 = min(y0 + 1, VH - 1);
    int z0 = (int)floorf(fzc); int z1 = min(z0 + 1, VD - 1);
    float wx = fxc - (float)x0;
    float wy = fyc - (float)y0;
    float wz = fzc - (float)z0;

    int zb0 = z0 >> 1, zb1 = z1 >> 1;
    bool o0 = (z0 & 1) != 0;      // select hi half for z0
    bool o1 = (z1 & 1) != 0;      // select hi half for z1

    // 8 half2 loads (issue all before use)
    __half2 a00 = g_E2[e2idx(y0, x0, zb0)];
    __half2 a01 = g_E2[e2idx(y0, x1, zb0)];
    __half2 a10 = g_E2[e2idx(y1, x0, zb0)];
    __half2 a11 = g_E2[e2idx(y1, x1, zb0)];
    __half2 b00 = g_E2[e2idx(y0, x0, zb1)];
    __half2 b01 = g_E2[e2idx(y0, x1, zb1)];
    __half2 b10 = g_E2[e2idx(y1, x0, zb1)];
    __half2 b11 = g_E2[e2idx(y1, x1, zb1)];

    float d000 = o0 ? __high2float(a00) : __low2float(a00); // z0,y0,x0
    float d001 = o0 ? __high2float(a01) : __low2float(a01); // z0,y0,x1
    float d010 = o0 ? __high2float(a10) : __low2float(a10); // z0,y1,x0
    float d011 = o0 ? __high2float(a11) : __low2float(a11); // z0,y1,x1
    float d100 = o1 ? __high2float(b00) : __low2float(b00); // z1,y0,x0
    float d101 = o1 ? __high2float(b01) : __low2float(b01); // z1,y0,x1
    float d110 = o1 ? __high2float(b10) : __low2float(b10); // z1,y1,x0
    float d111 = o1 ? __high2float(b11) : __low2float(b11); // z1,y1,x1

    float c00 = d000 + (d001 - d000) * wx;
    float c01 = d010 + (d011 - d010) * wx;
    float c10 = d100 + (d101 - d100) * wx;
    float c11 = d110 + (d111 - d110) * wx;
    float c0 = c00 + (c01 - c00) * wy;
    float c1 = c10 + (c11 - c10) * wy;
    out[i] = c0 + (c1 - c0) * wz;
}

extern "C" void kernel_launch(void* const* d_in, const int* in_sizes, int n_in,
                              void* d_out, int out_size) {
    const float* fv   = (const float*)d_in[0];  // feature_volume [1,1,256,240,320]
    const float* lmv  = (const float*)d_in[1];  // learnable_max_value [1,1,1,240,320]
    const float* intr = (const float*)d_in[2];  // [1,3,3]
    const float* pts  = (const float*)d_in[3];  // [1,8192,128,3]
    const int*   Hp   = (const int*)d_in[4];
    const int*   Wp   = (const int*)d_in[5];
    const int*   dmin = (const int*)d_in[6];
    const int*   dmax = (const int*)d_in[7];

    pass1_kernel<<<VH * XB, 256>>>(fv, lmv);   // 2400 blocks

    int n = out_size;  // 1*8192*128 points
    pass2_kernel<<<(n + 255) / 256, 256>>>(pts, intr, Hp, Wp, dmin, dmax,
                                           (float*)d_out, n);
}

// round 10
// speedup vs baseline: 1.6976x; 1.0596x over previous
#include <cuda_runtime.h>
#include <cuda_fp16.h>
#include <math.h>

#define VD 256
#define VH 240
#define VW 320
#define NPIX (VH * VW)
#define XB (VW / 32)      // 10 x-blocks of 32 x (= 16 xp)

// Density volume, fp16, 2x2 (x,z)-quad cells, non-redundant, 39.3 MB.
// Cell (y, xp, zp) as 64-bit word, bit offset of corner (xo, zo) = xo*32+zo*16:
//   bits[ 0:16) E(2xp,  2zp)   bits[16:32) E(2xp,  2zp+1)
//   bits[32:48) E(2xp+1,2zp)   bits[48:64) E(2xp+1,2zp+1)
// index = ((y*XB + (xp>>4))*128 + zp)*16 + (xp&15)
__device__ unsigned long long g_C[(size_t)VH * XB * 128 * 16];

__device__ __forceinline__ size_t cidx(int y, int xp, int zp) {
    return ((size_t)(y * XB + (xp >> 4)) * 128 + zp) * 16 + (xp & 15);
}

// ---------------------------------------------------------------------------
// Pass 1: block = (y, 32-x group), 256 threads. lane = x, warp w owns 32 z.
// exp values held in registers; softmax denom smem-reduced; cells assembled
// via shfl_xor(1) (even lane takes odd neighbor's half2) and stored as
// 16x8B = 128B coalesced warp stores.
// ---------------------------------------------------------------------------
__global__ void __launch_bounds__(256) pass1_kernel(const float* __restrict__ fv,
                                                    const float* __restrict__ lmv) {
    int blk  = blockIdx.x;            // y*XB + xb
    int y    = blk / XB;
    int xb   = blk - y * XB;
    int lane = threadIdx.x & 31;
    int wid  = threadIdx.x >> 5;
    int x    = (xb << 5) + lane;

    const float* p = fv + (size_t)y * VW + x;

    float e[32];
    float s = 0.f;
#pragma unroll
    for (int i = 0; i < 32; i++) {
        int z = (wid << 5) + i;
        e[i] = __expf(p[(size_t)z * NPIX]);
        s += e[i];
    }

    __shared__ float part[8][32];
    part[wid][lane] = s;
    __syncthreads();

    float tot = 0.f;
#pragma unroll
    for (int w = 0; w < 8; w++) tot += part[w][lane];

    float mv = lmv[y * VW + x];
    float K  = (fmaxf(mv, 0.f) + 0.01f) / tot;

    // warp w covers zp in [16w, 16w+16); even lanes write cells for xp = x>>1
    unsigned long long* dst = g_C + ((size_t)blk * 128 + (wid << 4)) * 16 + (lane >> 1);
    bool even = (lane & 1) == 0;
#pragma unroll
    for (int i = 0; i < 16; i++) {
        __half2 h = __floats2half2_rn(e[2 * i] * K, e[2 * i + 1] * K);
        unsigned int u = *(unsigned int*)&h;
        unsigned int v = __shfl_xor_sync(0xffffffffu, u, 1);
        if (even) dst[(size_t)i * 16] =
            (unsigned long long)u | ((unsigned long long)v << 32);
    }
}

// ---------------------------------------------------------------------------
// Pass 2: project point, trilinear-gather from quad-cell volume.
// Cells needed per y-plane = (#distinct xp) x (#distinct zp); predicated
// loads -> average active-lane requests = 2 * 1.5 * 1.5 = 4.5 per point.
// Corner extraction = one 64-bit shift + half->float convert.
// ---------------------------------------------------------------------------
__device__ __forceinline__ float pickq(unsigned long long c, int sh) {
    unsigned short bits = (unsigned short)(c >> sh);
    return __half2float(__ushort_as_half(bits));
}

__global__ void __launch_bounds__(256) pass2_kernel(const float* __restrict__ pts,
                                                    const float* __restrict__ intr,
                                                    const int* __restrict__ Hp,
                                                    const int* __restrict__ Wp,
                                                    const int* __restrict__ dminp,
                                                    const int* __restrict__ dmaxp,
                                                    float* __restrict__ out,
                                                    int n) {
    int i = blockIdx.x * blockDim.x + threadIdx.x;
    if (i >= n) return;

    float X = pts[3 * i + 0];
    float Y = pts[3 * i + 1];
    float Z = pts[3 * i + 2];

    float fx = intr[0], cx = intr[2];
    float fy = intr[4], cy = intr[5];
    float Himg = (float)(*Hp);
    float Wimg = (float)(*Wp);
    float dmin = (float)(*dminp);
    float dmax = (float)(*dmaxp);

    float px = fx * X + cx * Z;
    float py = fy * Y + cy * Z;
    float pz = Z;
    float inv_e = 1.0f / (pz + 1e-10f);
    float inv = 1.0f / pz;

    float gx = (px * inv_e / Wimg - 0.5f) * 2.0f;
    float gy = (py * inv_e / Himg - 0.5f) * 2.0f;
    float gz = ((inv - dmin) / (dmax - dmin) - 0.5f) * 2.0f;

    float fxc = fminf(fmaxf((gx + 1.0f) * 0.5f * (float)(VW - 1), 0.0f), (float)(VW - 1));
    float fyc = fminf(fmaxf((gy + 1.0f) * 0.5f * (float)(VH - 1), 0.0f), (float)(VH - 1));
    float fzc = fminf(fmaxf((gz + 1.0f) * 0.5f * (float)(VD - 1), 0.0f), (float)(VD - 1));

    int x0 = (int)floorf(fxc); int x1 = min(x0 + 1, VW - 1);
    int y0 = (int)floorf(fyc); int y1 = min(y0 + 1, VH - 1);
    int z0 = (int)floorf(fzc); int z1 = min(z0 + 1, VD - 1);
    float wx = fxc - (float)x0;
    float wy = fyc - (float)y0;
    float wz = fzc - (float)z0;

    int xpA = x0 >> 1, xpB = x1 >> 1;
    int zpA = z0 >> 1, zpB = z1 >> 1;
    bool xd = (xpB != xpA);
    bool zd = (zpB != zpA);
    int s00 = (x0 & 1) * 32 + (z0 & 1) * 16;   // shift for (x0, z0)
    int s10 = (x1 & 1) * 32 + (z0 & 1) * 16;   // (x1, z0)
    int s01 = (x0 & 1) * 32 + (z1 & 1) * 16;   // (x0, z1)
    int s11 = (x1 & 1) * 32 + (z1 & 1) * 16;   // (x1, z1)

    // y0 plane cells (predicated loads; duplicates reuse registers)
    unsigned long long aAA = g_C[cidx(y0, xpA, zpA)];
    unsigned long long aBA = xd ? g_C[cidx(y0, xpB, zpA)] : aAA;
    unsigned long long aAB = zd ? g_C[cidx(y0, xpA, zpB)] : aAA;
    unsigned long long aBB = (xd && zd) ? g_C[cidx(y0, xpB, zpB)]
                                        : (xd ? aBA : (zd ? aAB : aAA));
    // y1 plane cells
    unsigned long long bAA = g_C[cidx(y1, xpA, zpA)];
    unsigned long long bBA = xd ? g_C[cidx(y1, xpB, zpA)] : bAA;
    unsigned long long bAB = zd ? g_C[cidx(y1, xpA, zpB)] : bAA;
    unsigned long long bBB = (xd && zd) ? g_C[cidx(y1, xpB, zpB)]
                                        : (xd ? bBA : (zd ? bAB : bAA));

    // corners d{z}{y}{x}
    float d000 = pickq(aAA, s00);
    float d001 = pickq(aBA, s10);
    float d010 = pickq(bAA, s00);
    float d011 = pickq(bBA, s10);
    float d100 = pickq(aAB, s01);
    float d101 = pickq(aBB, s11);
    float d110 = pickq(bAB, s01);
    float d111 = pickq(bBB, s11);

    float c00 = d000 + (d001 - d000) * wx;
    float c01 = d010 + (d011 - d010) * wx;
    float c10 = d100 + (d101 - d100) * wx;
    float c11 = d110 + (d111 - d110) * wx;
    float c0 = c00 + (c01 - c00) * wy;
    float c1 = c10 + (c11 - c10) * wy;
    out[i] = c0 + (c1 - c0) * wz;
}

extern "C" void kernel_launch(void* const* d_in, const int* in_sizes, int n_in,
                              void* d_out, int out_size) {
    const float* fv   = (const float*)d_in[0];  // feature_volume [1,1,256,240,320]
    const float* lmv  = (const float*)d_in[1];  // learnable_max_value [1,1,1,240,320]
    const float* intr = (const float*)d_in[2];  // [1,3,3]
    const float* pts  = (const float*)d_in[3];  // [1,8192,128,3]
    const int*   Hp   = (const int*)d_in[4];
    const int*   Wp   = (const int*)d_in[5];
    const int*   dmin = (const int*)d_in[6];
    const int*   dmax = (const int*)d_in[7];

    pass1_kernel<<<VH * XB, 256>>>(fv, lmv);   // 2400 blocks

    int n = out_size;  // 1*8192*128 points
    pass2_kernel<<<(n + 255) / 256, 256>>>(pts, intr, Hp, Wp, dmin, dmax,
                                           (float*)d_out, n);
}